// round 16
// baseline (speedup 1.0000x reference)
#include <cuda_runtime.h>
#include <cuda_fp16.h>
#include <cstdint>

#define NN 100000
#define NE 1600000
#define NBLK_SCAN 98   // ceil(100000/1024)

// ---------------------------------------------------------------------------
// Scratch (static device arrays; allocation-free per harness rules).
// ---------------------------------------------------------------------------
__device__ __half g_S1h[(size_t)NN * 128]; // layer-1 support (fp16)
__device__ __half g_A1h[(size_t)NN * 128]; // layer-1 activation (fp16)
__device__ __half g_S2h[(size_t)NN * 64];  // layer-2 support (fp16)
__device__ __half g_A2h[(size_t)NN * 64];  // layer-2 activation (fp16)
__device__ __half g_S3h[(size_t)NN * 64];  // layer-3 support (fp16)
__device__ __half g_Wh[45056];             // fp16 weights, transposed (W1T|W2T|W3T)
__device__ int   g_cnt[NN];
__device__ int   g_pre[NN];
__device__ int   g_bsum[1024];
__device__ int   g_btop[1024];
__device__ int   g_rowptr[NN + 1];
__device__ int   g_cursor[NN];
__device__ int2  g_csr[NE];

// ---------------------------------------------------------------------------
// Helpers
// ---------------------------------------------------------------------------
__device__ __forceinline__ uint32_t smem_u32(const void* p) {
    uint32_t a;
    asm("{ .reg .u64 t; cvta.to.shared.u64 t, %1; cvt.u32.u64 %0, t; }" : "=r"(a) : "l"(p));
    return a;
}
__device__ __forceinline__ void cp16(uint32_t s, const void* g, bool pred) {
    asm volatile("cp.async.cg.shared.global [%0], [%1], 16, %2;"
                 :: "r"(s), "l"(g), "r"(pred ? 16 : 0));
}
#define CP_COMMIT() asm volatile("cp.async.commit_group;" ::: "memory")
#define CP_WAIT0()  asm volatile("cp.async.wait_group 0;" ::: "memory")
#define CP_WAIT1()  asm volatile("cp.async.wait_group 1;" ::: "memory")

__device__ __forceinline__ void ldsm4(uint32_t& r0, uint32_t& r1, uint32_t& r2, uint32_t& r3,
                                      uint32_t addr) {
    asm volatile("ldmatrix.sync.aligned.m8n8.x4.shared.b16 {%0,%1,%2,%3}, [%4];"
                 : "=r"(r0), "=r"(r1), "=r"(r2), "=r"(r3) : "r"(addr));
}
__device__ __forceinline__ void mma_f16(float* d, const uint32_t* a, const uint32_t* b) {
    asm volatile(
        "mma.sync.aligned.m16n8k16.row.col.f32.f16.f16.f32 "
        "{%0,%1,%2,%3}, {%4,%5,%6,%7}, {%8,%9}, {%0,%1,%2,%3};"
        : "+f"(d[0]), "+f"(d[1]), "+f"(d[2]), "+f"(d[3])
        : "r"(a[0]), "r"(a[1]), "r"(a[2]), "r"(a[3]), "r"(b[0]), "r"(b[1]));
}

// ---------------------------------------------------------------------------
// CSR build kernels (known good)
// ---------------------------------------------------------------------------
__global__ void zero_kernel(int* __restrict__ p, int n) {
    int i = blockIdx.x * blockDim.x + threadIdx.x;
    if (i < n) p[i] = 0;
}
__global__ void count_kernel(const int* __restrict__ dst, int* __restrict__ cnt, int E) {
    int e = blockIdx.x * blockDim.x + threadIdx.x;
    if (e < E) atomicAdd(&cnt[__ldg(&dst[e])], 1);
}
__global__ void scan_block_kernel(const int* __restrict__ in, int* __restrict__ outx,
                                  int* __restrict__ sums, int n) {
    __shared__ int s[2][1024];
    int tid = threadIdx.x;
    int i = blockIdx.x * 1024 + tid;
    int v = (i < n) ? in[i] : 0;
    int pin = 0;
    s[0][tid] = v;
    __syncthreads();
#pragma unroll
    for (int off = 1; off < 1024; off <<= 1) {
        int t = s[pin][tid] + ((tid >= off) ? s[pin][tid - off] : 0);
        s[pin ^ 1][tid] = t;
        pin ^= 1;
        __syncthreads();
    }
    if (i < n) outx[i] = s[pin][tid] - v;
    if (sums != nullptr && tid == 1023) sums[blockIdx.x] = s[pin][1023];
}
__global__ void add_offsets_kernel(const int* __restrict__ pre, const int* __restrict__ top,
                                   int* __restrict__ rowptr, int* __restrict__ cursor, int n) {
    int i = blockIdx.x * blockDim.x + threadIdx.x;
    if (i < n) {
        int v = pre[i] + __ldg(&top[i >> 10]);
        rowptr[i] = v;
        cursor[i] = v;
    }
    if (i == 0) rowptr[n] = NE;
}
__global__ void scatter_kernel(const int* __restrict__ src, const int* __restrict__ dst,
                               const float* __restrict__ w, int* __restrict__ cursor,
                               int2* __restrict__ csr, int E) {
    int e = blockIdx.x * blockDim.x + threadIdx.x;
    if (e >= E) return;
    int d = __ldg(&dst[e]);
    int pos = atomicAdd(&cursor[d], 1);
    csr[pos] = make_int2(__ldg(&src[e]), __float_as_int(__ldg(&w[e])));
}

// W[K,N] row-major -> fp16 [N,K] k-major
__global__ void wconv_kernel(const float* __restrict__ W, __half* __restrict__ Wh,
                             int K, int N) {
    int i = blockIdx.x * blockDim.x + threadIdx.x;
    if (i >= K * N) return;
    int n = i / K, k = i % K;
    Wh[(size_t)n * K + k] = __float2half_rn(__ldg(&W[(size_t)k * N + n]));
}

// ---------------------------------------------------------------------------
// HMMA fp16 GEMM: C[M,N_OUT] = A[M,K] @ B[N_OUT,K]^T, fp32 accum, fp16 out.
// AMODE 0: A fp32, converted in regs (pipelined LDG/STS).
// AMODE 1: A fp16 via cp.async.
// ---------------------------------------------------------------------------
template <int N_OUT, int K_TOTAL, int AMODE>
__global__ __launch_bounds__(256, 2)
void gemm_mma_kernel(const void* __restrict__ Ain, const __half* __restrict__ Bh,
                     __half* __restrict__ Cout, int M) {
    constexpr int NCH = K_TOTAL / 32;
    constexpr int ROWB = 80;
    constexpr int AT = 128 * ROWB;
    constexpr int BT = N_OUT * ROWB;
    constexpr int STAGE = AT + BT;
    constexpr int WN = N_OUT / 4;
    constexpr int NF = WN / 8;

    extern __shared__ char smem[];
    const uint32_t sb = smem_u32(smem);
    const int tid = threadIdx.x;
    const int wid = tid >> 5, lane = tid & 31;
    const int wm = wid & 1, wn = wid >> 1;
    const int bm = blockIdx.x * 128;
    const int lrow = lane & 7;
    const int lmat = lane >> 3;

    float acc[4][NF][4];
#pragma unroll
    for (int mf = 0; mf < 4; mf++)
#pragma unroll
        for (int nf = 0; nf < NF; nf++)
#pragma unroll
            for (int j = 0; j < 4; j++) acc[mf][nf][j] = 0.f;

    float4 paf[4];

    auto ldgA = [&](int ch) {
        const float* Af = (const float*)Ain;
#pragma unroll
        for (int i = 0; i < 4; i++) {
            int idx = tid + i * 256;
            int row = idx >> 3, seg = idx & 7;
            paf[i] = make_float4(0.f, 0.f, 0.f, 0.f);
            if (bm + row < M)
                paf[i] = __ldg((const float4*)&Af[(size_t)(bm + row) * K_TOTAL + ch * 32 + seg * 4]);
        }
    };
    auto stsA = [&](int st) {
#pragma unroll
        for (int i = 0; i < 4; i++) {
            int idx = tid + i * 256;
            int row = idx >> 3, seg = idx & 7;
            float4 v = paf[i];
            __half2 h0 = __floats2half2_rn(v.x, v.y);
            __half2 h1 = __floats2half2_rn(v.z, v.w);
            uint2 h = make_uint2(*(unsigned*)&h0, *(unsigned*)&h1);
            *(uint2*)(smem + st * STAGE + row * ROWB + seg * 8) = h;
        }
    };
    auto loadA_cp = [&](int ch, int st) {
        const __half* Ah = (const __half*)Ain;
        const uint32_t base = sb + st * STAGE;
#pragma unroll
        for (int i = 0; i < 2; i++) {
            int idx = tid + i * 256;
            int row = idx >> 2, seg = idx & 3;
            bool p = (bm + row) < M;
            cp16(base + row * ROWB + seg * 16,
                 Ah + (size_t)(bm + row) * K_TOTAL + ch * 32 + seg * 8, p);
        }
    };
    auto loadB = [&](int ch, int st) {
        const uint32_t base = sb + st * STAGE;
#pragma unroll
        for (int i = 0; i < (N_OUT * 4) / 256; i++) {
            int idx = tid + i * 256;
            int row = idx >> 2, seg = idx & 3;
            cp16(base + AT + row * ROWB + seg * 16,
                 Bh + (size_t)row * K_TOTAL + ch * 32 + seg * 8, true);
        }
        CP_COMMIT();
    };
    auto compute = [&](int st) {
        const uint32_t aB = sb + st * STAGE;
        const uint32_t bB = aB + AT;
#pragma unroll
        for (int ks = 0; ks < 2; ks++) {
            const int seg = 2 * ks + (lmat >> 1);
            uint32_t bf[NF][2];
#pragma unroll
            for (int p = 0; p < NF / 2; p++) {
                int nrow = wn * WN + p * 16 + lrow + (lmat & 1) * 8;
                uint32_t off = nrow * ROWB + seg * 16;
                uint32_t r0, r1, r2, r3;
                ldsm4(r0, r1, r2, r3, bB + off);
                bf[2 * p][0] = r0; bf[2 * p + 1][0] = r1;
                bf[2 * p][1] = r2; bf[2 * p + 1][1] = r3;
            }
#pragma unroll
            for (int mf = 0; mf < 4; mf++) {
                int arow = wm * 64 + mf * 16 + lrow + (lmat & 1) * 8;
                uint32_t off = arow * ROWB + seg * 16;
                uint32_t af[4];
                ldsm4(af[0], af[1], af[2], af[3], aB + off);
#pragma unroll
                for (int nf = 0; nf < NF; nf++)
                    mma_f16(acc[mf][nf], af, bf[nf]);
            }
        }
    };

    if (AMODE == 0) {
        ldgA(0);
        stsA(0);
        loadB(0, 0);
        CP_WAIT0();
        __syncthreads();
        for (int c = 0; c < NCH; c++) {
            bool more = (c + 1) < NCH;
            if (more) { ldgA(c + 1); loadB(c + 1, (c + 1) & 1); }
            compute(c & 1);
            if (more) {
                stsA((c + 1) & 1);
                CP_WAIT0();
                __syncthreads();
            }
        }
    } else {
        loadA_cp(0, 0);
        loadB(0, 0);
        for (int c = 0; c < NCH; c++) {
            if (c + 1 < NCH) {
                loadA_cp(c + 1, (c + 1) & 1);
                loadB(c + 1, (c + 1) & 1);
                CP_WAIT1();
            } else {
                CP_WAIT0();
            }
            __syncthreads();
            compute(c & 1);
            __syncthreads();
        }
    }

    const int r0 = lane >> 2;
    const int c0 = (lane & 3) * 2;
#pragma unroll
    for (int mf = 0; mf < 4; mf++) {
        int row = bm + wm * 64 + mf * 16 + r0;
#pragma unroll
        for (int half = 0; half < 2; half++) {
            int rr = row + half * 8;
            if (rr < M) {
#pragma unroll
                for (int nf = 0; nf < NF; nf++) {
                    int col = wn * WN + nf * 8 + c0;
                    __half2 hv = __floats2half2_rn(acc[mf][nf][half * 2],
                                                   acc[mf][nf][half * 2 + 1]);
                    *(__half2*)&Cout[(size_t)rr * N_OUT + col] = hv;
                }
            }
        }
    }
}

// ---------------------------------------------------------------------------
// CSR pull-mode SpMM over fp16 support, 4-way unrolled (MLP=4), streaming
// gathers (__ldcs), fused bias+relu, fp16 activation out.
// ---------------------------------------------------------------------------
template <int D>
__global__ void spmm_h_kernel(const __half* __restrict__ S, const int2* __restrict__ csr,
                              const int* __restrict__ rowptr, const float* __restrict__ bias,
                              __half* __restrict__ outA) {
    int warp = (blockIdx.x * blockDim.x + threadIdx.x) >> 5;
    int lane = threadIdx.x & 31;
    if (warp >= NN) return;
    int start = __ldg(&rowptr[warp]);
    int end = __ldg(&rowptr[warp + 1]);

    if (D == 128) {
        float4 acc = __ldg((const float4*)bias + lane);
        int e = start;
        for (; e + 3 < end; e += 4) {
            int2 r0 = __ldg(&csr[e]);
            int2 r1 = __ldg(&csr[e + 1]);
            int2 r2 = __ldg(&csr[e + 2]);
            int2 r3 = __ldg(&csr[e + 3]);
            uint2 q0 = __ldcs((const uint2*)(S + (size_t)r0.x * 128) + lane);
            uint2 q1 = __ldcs((const uint2*)(S + (size_t)r1.x * 128) + lane);
            uint2 q2 = __ldcs((const uint2*)(S + (size_t)r2.x * 128) + lane);
            uint2 q3 = __ldcs((const uint2*)(S + (size_t)r3.x * 128) + lane);
            float w0 = __int_as_float(r0.y), w1 = __int_as_float(r1.y);
            float w2 = __int_as_float(r2.y), w3 = __int_as_float(r3.y);
            float2 a, b;
            a = __half22float2(*(__half2*)&q0.x); b = __half22float2(*(__half2*)&q0.y);
            acc.x = fmaf(w0, a.x, acc.x); acc.y = fmaf(w0, a.y, acc.y);
            acc.z = fmaf(w0, b.x, acc.z); acc.w = fmaf(w0, b.y, acc.w);
            a = __half22float2(*(__half2*)&q1.x); b = __half22float2(*(__half2*)&q1.y);
            acc.x = fmaf(w1, a.x, acc.x); acc.y = fmaf(w1, a.y, acc.y);
            acc.z = fmaf(w1, b.x, acc.z); acc.w = fmaf(w1, b.y, acc.w);
            a = __half22float2(*(__half2*)&q2.x); b = __half22float2(*(__half2*)&q2.y);
            acc.x = fmaf(w2, a.x, acc.x); acc.y = fmaf(w2, a.y, acc.y);
            acc.z = fmaf(w2, b.x, acc.z); acc.w = fmaf(w2, b.y, acc.w);
            a = __half22float2(*(__half2*)&q3.x); b = __half22float2(*(__half2*)&q3.y);
            acc.x = fmaf(w3, a.x, acc.x); acc.y = fmaf(w3, a.y, acc.y);
            acc.z = fmaf(w3, b.x, acc.z); acc.w = fmaf(w3, b.y, acc.w);
        }
        for (; e < end; e++) {
            int2 r0 = __ldg(&csr[e]);
            uint2 q0 = __ldcs((const uint2*)(S + (size_t)r0.x * 128) + lane);
            float w0 = __int_as_float(r0.y);
            float2 a = __half22float2(*(__half2*)&q0.x);
            float2 b = __half22float2(*(__half2*)&q0.y);
            acc.x = fmaf(w0, a.x, acc.x); acc.y = fmaf(w0, a.y, acc.y);
            acc.z = fmaf(w0, b.x, acc.z); acc.w = fmaf(w0, b.y, acc.w);
        }
        acc.x = fmaxf(acc.x, 0.f); acc.y = fmaxf(acc.y, 0.f);
        acc.z = fmaxf(acc.z, 0.f); acc.w = fmaxf(acc.w, 0.f);
        uint2 o;
        __half2 h0 = __floats2half2_rn(acc.x, acc.y);
        __half2 h1 = __floats2half2_rn(acc.z, acc.w);
        o.x = *(unsigned*)&h0;
        o.y = *(unsigned*)&h1;
        ((uint2*)(outA + (size_t)warp * 128))[lane] = o;
    } else {
        float2 acc = __ldg((const float2*)bias + lane);
        int e = start;
        for (; e + 3 < end; e += 4) {
            int2 r0 = __ldg(&csr[e]);
            int2 r1 = __ldg(&csr[e + 1]);
            int2 r2 = __ldg(&csr[e + 2]);
            int2 r3 = __ldg(&csr[e + 3]);
            unsigned q0 = __ldcs((const unsigned*)(S + (size_t)r0.x * 64) + lane);
            unsigned q1 = __ldcs((const unsigned*)(S + (size_t)r1.x * 64) + lane);
            unsigned q2 = __ldcs((const unsigned*)(S + (size_t)r2.x * 64) + lane);
            unsigned q3 = __ldcs((const unsigned*)(S + (size_t)r3.x * 64) + lane);
            float w0 = __int_as_float(r0.y), w1 = __int_as_float(r1.y);
            float w2 = __int_as_float(r2.y), w3 = __int_as_float(r3.y);
            float2 v;
            v = __half22float2(*(__half2*)&q0);
            acc.x = fmaf(w0, v.x, acc.x); acc.y = fmaf(w0, v.y, acc.y);
            v = __half22float2(*(__half2*)&q1);
            acc.x = fmaf(w1, v.x, acc.x); acc.y = fmaf(w1, v.y, acc.y);
            v = __half22float2(*(__half2*)&q2);
            acc.x = fmaf(w2, v.x, acc.x); acc.y = fmaf(w2, v.y, acc.y);
            v = __half22float2(*(__half2*)&q3);
            acc.x = fmaf(w3, v.x, acc.x); acc.y = fmaf(w3, v.y, acc.y);
        }
        for (; e < end; e++) {
            int2 r0 = __ldg(&csr[e]);
            unsigned q0 = __ldcs((const unsigned*)(S + (size_t)r0.x * 64) + lane);
            float w0 = __int_as_float(r0.y);
            float2 v = __half22float2(*(__half2*)&q0);
            acc.x = fmaf(w0, v.x, acc.x); acc.y = fmaf(w0, v.y, acc.y);
        }
        acc.x = fmaxf(acc.x, 0.f); acc.y = fmaxf(acc.y, 0.f);
        __half2 h0 = __floats2half2_rn(acc.x, acc.y);
        ((unsigned*)(outA + (size_t)warp * 64))[lane] = *(unsigned*)&h0;
    }
}

// ---------------------------------------------------------------------------
// Final-layer SpMM: fp16 gather (4-way unrolled, streaming), fp32 out.
// ---------------------------------------------------------------------------
__global__ void spmm_final_kernel(const __half* __restrict__ S, const int2* __restrict__ csr,
                                  const int* __restrict__ rowptr, const float* __restrict__ bias,
                                  float* __restrict__ out) {
    int warp = (blockIdx.x * blockDim.x + threadIdx.x) >> 5;
    int lane = threadIdx.x & 31;
    if (warp >= NN) return;
    int start = __ldg(&rowptr[warp]);
    int end = __ldg(&rowptr[warp + 1]);
    float2 acc = __ldg((const float2*)bias + lane);
    int e = start;
    for (; e + 3 < end; e += 4) {
        int2 r0 = __ldg(&csr[e]);
        int2 r1 = __ldg(&csr[e + 1]);
        int2 r2 = __ldg(&csr[e + 2]);
        int2 r3 = __ldg(&csr[e + 3]);
        unsigned q0 = __ldcs((const unsigned*)(S + (size_t)r0.x * 64) + lane);
        unsigned q1 = __ldcs((const unsigned*)(S + (size_t)r1.x * 64) + lane);
        unsigned q2 = __ldcs((const unsigned*)(S + (size_t)r2.x * 64) + lane);
        unsigned q3 = __ldcs((const unsigned*)(S + (size_t)r3.x * 64) + lane);
        float w0 = __int_as_float(r0.y), w1 = __int_as_float(r1.y);
        float w2 = __int_as_float(r2.y), w3 = __int_as_float(r3.y);
        float2 v;
        v = __half22float2(*(__half2*)&q0);
        acc.x = fmaf(w0, v.x, acc.x); acc.y = fmaf(w0, v.y, acc.y);
        v = __half22float2(*(__half2*)&q1);
        acc.x = fmaf(w1, v.x, acc.x); acc.y = fmaf(w1, v.y, acc.y);
        v = __half22float2(*(__half2*)&q2);
        acc.x = fmaf(w2, v.x, acc.x); acc.y = fmaf(w2, v.y, acc.y);
        v = __half22float2(*(__half2*)&q3);
        acc.x = fmaf(w3, v.x, acc.x); acc.y = fmaf(w3, v.y, acc.y);
    }
    for (; e < end; e++) {
        int2 r0 = __ldg(&csr[e]);
        unsigned q0 = __ldcs((const unsigned*)(S + (size_t)r0.x * 64) + lane);
        float w0 = __int_as_float(r0.y);
        float2 v = __half22float2(*(__half2*)&q0);
        acc.x = fmaf(w0, v.x, acc.x); acc.y = fmaf(w0, v.y, acc.y);
    }
    *((float2*)(out + (size_t)warp * 64) + lane) = acc;
}

// ---------------------------------------------------------------------------
extern "C" void kernel_launch(void* const* d_in, const int* in_sizes, int n_in,
                              void* d_out, int out_size) {
    const float* x    = (const float*)d_in[0];
    const int*   esrc = (const int*)d_in[1];
    const int*   edst = (const int*)d_in[2];
    const float* ew   = (const float*)d_in[3];
    const float* W1   = (const float*)d_in[4];
    const float* b1   = (const float*)d_in[5];
    const float* W2   = (const float*)d_in[6];
    const float* b2   = (const float*)d_in[7];
    const float* W3   = (const float*)d_in[8];
    const float* b3   = (const float*)d_in[9];
    float* out = (float*)d_out;

    __half *S1h, *A1h, *S2h, *A2h, *S3h, *Wh;
    int *cnt, *pre, *bsum, *btop, *rowptr, *cursor;
    int2* csr;
    cudaGetSymbolAddress((void**)&S1h, g_S1h);
    cudaGetSymbolAddress((void**)&A1h, g_A1h);
    cudaGetSymbolAddress((void**)&S2h, g_S2h);
    cudaGetSymbolAddress((void**)&A2h, g_A2h);
    cudaGetSymbolAddress((void**)&S3h, g_S3h);
    cudaGetSymbolAddress((void**)&Wh, g_Wh);
    cudaGetSymbolAddress((void**)&cnt, g_cnt);
    cudaGetSymbolAddress((void**)&pre, g_pre);
    cudaGetSymbolAddress((void**)&bsum, g_bsum);
    cudaGetSymbolAddress((void**)&btop, g_btop);
    cudaGetSymbolAddress((void**)&rowptr, g_rowptr);
    cudaGetSymbolAddress((void**)&cursor, g_cursor);
    cudaGetSymbolAddress((void**)&csr, g_csr);

    static cudaStream_t s2strm = nullptr;
    static cudaEvent_t evFork = nullptr, evJoin = nullptr;
    if (s2strm == nullptr) {
        cudaStreamCreateWithFlags(&s2strm, cudaStreamNonBlocking);
        cudaEventCreateWithFlags(&evFork, cudaEventDisableTiming);
        cudaEventCreateWithFlags(&evJoin, cudaEventDisableTiming);
    }

    const int E = NE, M = NN;
    const int gx = (M + 127) / 128;

    cudaFuncSetAttribute(gemm_mma_kernel<128, 256, 0>,
                         cudaFuncAttributeMaxDynamicSharedMemorySize, 40960);
    cudaFuncSetAttribute(gemm_mma_kernel<64, 128, 1>,
                         cudaFuncAttributeMaxDynamicSharedMemorySize, 30720);
    cudaFuncSetAttribute(gemm_mma_kernel<64, 64, 1>,
                         cudaFuncAttributeMaxDynamicSharedMemorySize, 30720);

    // ----- Fork: CSR build + W2/W3 converts on side stream -----
    cudaEventRecord(evFork, 0);
    cudaStreamWaitEvent(s2strm, evFork, 0);
    zero_kernel<<<(NN + 511) / 512, 512, 0, s2strm>>>(cnt, NN);
    count_kernel<<<(E + 511) / 512, 512, 0, s2strm>>>(edst, cnt, E);
    scan_block_kernel<<<NBLK_SCAN, 1024, 0, s2strm>>>(cnt, pre, bsum, NN);
    scan_block_kernel<<<1, 1024, 0, s2strm>>>(bsum, btop, nullptr, NBLK_SCAN);
    add_offsets_kernel<<<(NN + 511) / 512, 512, 0, s2strm>>>(pre, btop, rowptr, cursor, NN);
    scatter_kernel<<<(E + 511) / 512, 512, 0, s2strm>>>(esrc, edst, ew, cursor, csr, E);
    wconv_kernel<<<(128 * 64 + 255) / 256, 256, 0, s2strm>>>(W2, Wh + 32768, 128, 64);
    wconv_kernel<<<(64 * 64 + 255) / 256, 256, 0, s2strm>>>(W3, Wh + 40960, 64, 64);
    cudaEventRecord(evJoin, s2strm);

    // ----- Main: W1 convert + GEMM1 (fp32 x -> fp16 S1) -----
    wconv_kernel<<<(256 * 128 + 255) / 256, 256>>>(W1, Wh, 256, 128);
    gemm_mma_kernel<128, 256, 0><<<gx, 256, 40960>>>(x, Wh, S1h, M);

    // ----- Join, then Layer 1 SpMM -----
    cudaStreamWaitEvent(0, evJoin, 0);
    spmm_h_kernel<128><<<(NN + 7) / 8, 256>>>(S1h, csr, rowptr, b1, A1h);

    // ----- Layer 2 -----
    gemm_mma_kernel<64, 128, 1><<<gx, 256, 30720>>>(A1h, Wh + 32768, S2h, M);
    spmm_h_kernel<64><<<(NN + 7) / 8, 256>>>(S2h, csr, rowptr, b2, A2h);

    // ----- Layer 3 -----
    gemm_mma_kernel<64, 64, 1><<<gx, 256, 30720>>>(A2h, Wh + 40960, S3h, M);
    spmm_final_kernel<<<(NN + 7) / 8, 256>>>(S3h, csr, rowptr, b3, out);
}

// round 17
// speedup vs baseline: 1.1110x; 1.1110x over previous
#include <cuda_runtime.h>
#include <cuda_fp16.h>
#include <cstdint>

#define NN 100000
#define NE 1600000
#define NBLK_SCAN 98   // ceil(100000/1024)

// ---------------------------------------------------------------------------
// Scratch (static device arrays; allocation-free per harness rules).
// ---------------------------------------------------------------------------
__device__ __half g_S1h[(size_t)NN * 128]; // layer-1 support (fp16)
__device__ __half g_A1h[(size_t)NN * 128]; // layer-1 activation (fp16)
__device__ __half g_S2h[(size_t)NN * 64];  // layer-2 support (fp16)
__device__ __half g_A2h[(size_t)NN * 64];  // layer-2 activation (fp16)
__device__ __half g_S3h[(size_t)NN * 64];  // layer-3 support (fp16)
__device__ __half g_Wh[45056];             // fp16 weights, transposed (W1T|W2T|W3T)
__device__ int   g_cnt[NN];
__device__ int   g_pre[NN];
__device__ int   g_bsum[1024];
__device__ int   g_btop[1024];
__device__ int   g_rowptr[NN + 1];
__device__ int   g_cursor[NN];
__device__ int2  g_csr[NE];

// ---------------------------------------------------------------------------
// Helpers
// ---------------------------------------------------------------------------
__device__ __forceinline__ uint32_t smem_u32(const void* p) {
    uint32_t a;
    asm("{ .reg .u64 t; cvta.to.shared.u64 t, %1; cvt.u32.u64 %0, t; }" : "=r"(a) : "l"(p));
    return a;
}
__device__ __forceinline__ void cp16(uint32_t s, const void* g, bool pred) {
    asm volatile("cp.async.cg.shared.global [%0], [%1], 16, %2;"
                 :: "r"(s), "l"(g), "r"(pred ? 16 : 0));
}
#define CP_COMMIT() asm volatile("cp.async.commit_group;" ::: "memory")
#define CP_WAIT0()  asm volatile("cp.async.wait_group 0;" ::: "memory")
#define CP_WAIT1()  asm volatile("cp.async.wait_group 1;" ::: "memory")

__device__ __forceinline__ void ldsm4(uint32_t& r0, uint32_t& r1, uint32_t& r2, uint32_t& r3,
                                      uint32_t addr) {
    asm volatile("ldmatrix.sync.aligned.m8n8.x4.shared.b16 {%0,%1,%2,%3}, [%4];"
                 : "=r"(r0), "=r"(r1), "=r"(r2), "=r"(r3) : "r"(addr));
}
__device__ __forceinline__ void mma_f16(float* d, const uint32_t* a, const uint32_t* b) {
    asm volatile(
        "mma.sync.aligned.m16n8k16.row.col.f32.f16.f16.f32 "
        "{%0,%1,%2,%3}, {%4,%5,%6,%7}, {%8,%9}, {%0,%1,%2,%3};"
        : "+f"(d[0]), "+f"(d[1]), "+f"(d[2]), "+f"(d[3])
        : "r"(a[0]), "r"(a[1]), "r"(a[2]), "r"(a[3]), "r"(b[0]), "r"(b[1]));
}

// ---------------------------------------------------------------------------
// CSR build kernels (known good)
// ---------------------------------------------------------------------------
__global__ void zero_kernel(int* __restrict__ p, int n) {
    int i = blockIdx.x * blockDim.x + threadIdx.x;
    if (i < n) p[i] = 0;
}
__global__ void count_kernel(const int* __restrict__ dst, int* __restrict__ cnt, int E) {
    int e = blockIdx.x * blockDim.x + threadIdx.x;
    if (e < E) atomicAdd(&cnt[__ldg(&dst[e])], 1);
}
__global__ void scan_block_kernel(const int* __restrict__ in, int* __restrict__ outx,
                                  int* __restrict__ sums, int n) {
    __shared__ int s[2][1024];
    int tid = threadIdx.x;
    int i = blockIdx.x * 1024 + tid;
    int v = (i < n) ? in[i] : 0;
    int pin = 0;
    s[0][tid] = v;
    __syncthreads();
#pragma unroll
    for (int off = 1; off < 1024; off <<= 1) {
        int t = s[pin][tid] + ((tid >= off) ? s[pin][tid - off] : 0);
        s[pin ^ 1][tid] = t;
        pin ^= 1;
        __syncthreads();
    }
    if (i < n) outx[i] = s[pin][tid] - v;
    if (sums != nullptr && tid == 1023) sums[blockIdx.x] = s[pin][1023];
}
__global__ void add_offsets_kernel(const int* __restrict__ pre, const int* __restrict__ top,
                                   int* __restrict__ rowptr, int* __restrict__ cursor, int n) {
    int i = blockIdx.x * blockDim.x + threadIdx.x;
    if (i < n) {
        int v = pre[i] + __ldg(&top[i >> 10]);
        rowptr[i] = v;
        cursor[i] = v;
    }
    if (i == 0) rowptr[n] = NE;
}
__global__ void scatter_kernel(const int* __restrict__ src, const int* __restrict__ dst,
                               const float* __restrict__ w, int* __restrict__ cursor,
                               int2* __restrict__ csr, int E) {
    int e = blockIdx.x * blockDim.x + threadIdx.x;
    if (e >= E) return;
    int d = __ldg(&dst[e]);
    int pos = atomicAdd(&cursor[d], 1);
    csr[pos] = make_int2(__ldg(&src[e]), __float_as_int(__ldg(&w[e])));
}

// W[K,N] row-major -> fp16 [N,K] k-major
__global__ void wconv_kernel(const float* __restrict__ W, __half* __restrict__ Wh,
                             int K, int N) {
    int i = blockIdx.x * blockDim.x + threadIdx.x;
    if (i >= K * N) return;
    int n = i / K, k = i % K;
    Wh[(size_t)n * K + k] = __float2half_rn(__ldg(&W[(size_t)k * N + n]));
}

// ---------------------------------------------------------------------------
// HMMA fp16 GEMM: C[M,N_OUT] = A[M,K] @ B[N_OUT,K]^T, fp32 accum, fp16 out.
// AMODE 0: A fp32, converted in regs (pipelined LDG/STS).
// AMODE 1: A fp16 via cp.async.
// ---------------------------------------------------------------------------
template <int N_OUT, int K_TOTAL, int AMODE>
__global__ __launch_bounds__(256, 2)
void gemm_mma_kernel(const void* __restrict__ Ain, const __half* __restrict__ Bh,
                     __half* __restrict__ Cout, int M) {
    constexpr int NCH = K_TOTAL / 32;
    constexpr int ROWB = 80;
    constexpr int AT = 128 * ROWB;
    constexpr int BT = N_OUT * ROWB;
    constexpr int STAGE = AT + BT;
    constexpr int WN = N_OUT / 4;
    constexpr int NF = WN / 8;

    extern __shared__ char smem[];
    const uint32_t sb = smem_u32(smem);
    const int tid = threadIdx.x;
    const int wid = tid >> 5, lane = tid & 31;
    const int wm = wid & 1, wn = wid >> 1;
    const int bm = blockIdx.x * 128;
    const int lrow = lane & 7;
    const int lmat = lane >> 3;

    float acc[4][NF][4];
#pragma unroll
    for (int mf = 0; mf < 4; mf++)
#pragma unroll
        for (int nf = 0; nf < NF; nf++)
#pragma unroll
            for (int j = 0; j < 4; j++) acc[mf][nf][j] = 0.f;

    float4 paf[4];

    auto ldgA = [&](int ch) {
        const float* Af = (const float*)Ain;
#pragma unroll
        for (int i = 0; i < 4; i++) {
            int idx = tid + i * 256;
            int row = idx >> 3, seg = idx & 7;
            paf[i] = make_float4(0.f, 0.f, 0.f, 0.f);
            if (bm + row < M)
                paf[i] = __ldg((const float4*)&Af[(size_t)(bm + row) * K_TOTAL + ch * 32 + seg * 4]);
        }
    };
    auto stsA = [&](int st) {
#pragma unroll
        for (int i = 0; i < 4; i++) {
            int idx = tid + i * 256;
            int row = idx >> 3, seg = idx & 7;
            float4 v = paf[i];
            __half2 h0 = __floats2half2_rn(v.x, v.y);
            __half2 h1 = __floats2half2_rn(v.z, v.w);
            uint2 h = make_uint2(*(unsigned*)&h0, *(unsigned*)&h1);
            *(uint2*)(smem + st * STAGE + row * ROWB + seg * 8) = h;
        }
    };
    auto loadA_cp = [&](int ch, int st) {
        const __half* Ah = (const __half*)Ain;
        const uint32_t base = sb + st * STAGE;
#pragma unroll
        for (int i = 0; i < 2; i++) {
            int idx = tid + i * 256;
            int row = idx >> 2, seg = idx & 3;
            bool p = (bm + row) < M;
            cp16(base + row * ROWB + seg * 16,
                 Ah + (size_t)(bm + row) * K_TOTAL + ch * 32 + seg * 8, p);
        }
    };
    auto loadB = [&](int ch, int st) {
        const uint32_t base = sb + st * STAGE;
#pragma unroll
        for (int i = 0; i < (N_OUT * 4) / 256; i++) {
            int idx = tid + i * 256;
            int row = idx >> 2, seg = idx & 3;
            cp16(base + AT + row * ROWB + seg * 16,
                 Bh + (size_t)row * K_TOTAL + ch * 32 + seg * 8, true);
        }
        CP_COMMIT();
    };
    auto compute = [&](int st) {
        const uint32_t aB = sb + st * STAGE;
        const uint32_t bB = aB + AT;
#pragma unroll
        for (int ks = 0; ks < 2; ks++) {
            const int seg = 2 * ks + (lmat >> 1);
            uint32_t bf[NF][2];
#pragma unroll
            for (int p = 0; p < NF / 2; p++) {
                int nrow = wn * WN + p * 16 + lrow + (lmat & 1) * 8;
                uint32_t off = nrow * ROWB + seg * 16;
                uint32_t r0, r1, r2, r3;
                ldsm4(r0, r1, r2, r3, bB + off);
                bf[2 * p][0] = r0; bf[2 * p + 1][0] = r1;
                bf[2 * p][1] = r2; bf[2 * p + 1][1] = r3;
            }
#pragma unroll
            for (int mf = 0; mf < 4; mf++) {
                int arow = wm * 64 + mf * 16 + lrow + (lmat & 1) * 8;
                uint32_t off = arow * ROWB + seg * 16;
                uint32_t af[4];
                ldsm4(af[0], af[1], af[2], af[3], aB + off);
#pragma unroll
                for (int nf = 0; nf < NF; nf++)
                    mma_f16(acc[mf][nf], af, bf[nf]);
            }
        }
    };

    if (AMODE == 0) {
        ldgA(0);
        stsA(0);
        loadB(0, 0);
        CP_WAIT0();
        __syncthreads();
        for (int c = 0; c < NCH; c++) {
            bool more = (c + 1) < NCH;
            if (more) { ldgA(c + 1); loadB(c + 1, (c + 1) & 1); }
            compute(c & 1);
            if (more) {
                stsA((c + 1) & 1);
                CP_WAIT0();
                __syncthreads();
            }
        }
    } else {
        loadA_cp(0, 0);
        loadB(0, 0);
        for (int c = 0; c < NCH; c++) {
            if (c + 1 < NCH) {
                loadA_cp(c + 1, (c + 1) & 1);
                loadB(c + 1, (c + 1) & 1);
                CP_WAIT1();
            } else {
                CP_WAIT0();
            }
            __syncthreads();
            compute(c & 1);
            __syncthreads();
        }
    }

    const int r0 = lane >> 2;
    const int c0 = (lane & 3) * 2;
#pragma unroll
    for (int mf = 0; mf < 4; mf++) {
        int row = bm + wm * 64 + mf * 16 + r0;
#pragma unroll
        for (int half = 0; half < 2; half++) {
            int rr = row + half * 8;
            if (rr < M) {
#pragma unroll
                for (int nf = 0; nf < NF; nf++) {
                    int col = wn * WN + nf * 8 + c0;
                    __half2 hv = __floats2half2_rn(acc[mf][nf][half * 2],
                                                   acc[mf][nf][half * 2 + 1]);
                    *(__half2*)&Cout[(size_t)rr * N_OUT + col] = hv;
                }
            }
        }
    }
}

// ---------------------------------------------------------------------------
// CSR pull-mode SpMM over fp16 support, 4-way unrolled (MLP=4, default-cached
// gathers), fused bias+relu, fp16 activation out.
// ---------------------------------------------------------------------------
template <int D>
__global__ void spmm_h_kernel(const __half* __restrict__ S, const int2* __restrict__ csr,
                              const int* __restrict__ rowptr, const float* __restrict__ bias,
                              __half* __restrict__ outA) {
    int warp = (blockIdx.x * blockDim.x + threadIdx.x) >> 5;
    int lane = threadIdx.x & 31;
    if (warp >= NN) return;
    int start = __ldg(&rowptr[warp]);
    int end = __ldg(&rowptr[warp + 1]);

    if (D == 128) {
        float4 acc = __ldg((const float4*)bias + lane);
        int e = start;
        for (; e + 3 < end; e += 4) {
            int2 r0 = __ldg(&csr[e]);
            int2 r1 = __ldg(&csr[e + 1]);
            int2 r2 = __ldg(&csr[e + 2]);
            int2 r3 = __ldg(&csr[e + 3]);
            uint2 q0 = __ldg((const uint2*)(S + (size_t)r0.x * 128) + lane);
            uint2 q1 = __ldg((const uint2*)(S + (size_t)r1.x * 128) + lane);
            uint2 q2 = __ldg((const uint2*)(S + (size_t)r2.x * 128) + lane);
            uint2 q3 = __ldg((const uint2*)(S + (size_t)r3.x * 128) + lane);
            float w0 = __int_as_float(r0.y), w1 = __int_as_float(r1.y);
            float w2 = __int_as_float(r2.y), w3 = __int_as_float(r3.y);
            float2 a, b;
            a = __half22float2(*(__half2*)&q0.x); b = __half22float2(*(__half2*)&q0.y);
            acc.x = fmaf(w0, a.x, acc.x); acc.y = fmaf(w0, a.y, acc.y);
            acc.z = fmaf(w0, b.x, acc.z); acc.w = fmaf(w0, b.y, acc.w);
            a = __half22float2(*(__half2*)&q1.x); b = __half22float2(*(__half2*)&q1.y);
            acc.x = fmaf(w1, a.x, acc.x); acc.y = fmaf(w1, a.y, acc.y);
            acc.z = fmaf(w1, b.x, acc.z); acc.w = fmaf(w1, b.y, acc.w);
            a = __half22float2(*(__half2*)&q2.x); b = __half22float2(*(__half2*)&q2.y);
            acc.x = fmaf(w2, a.x, acc.x); acc.y = fmaf(w2, a.y, acc.y);
            acc.z = fmaf(w2, b.x, acc.z); acc.w = fmaf(w2, b.y, acc.w);
            a = __half22float2(*(__half2*)&q3.x); b = __half22float2(*(__half2*)&q3.y);
            acc.x = fmaf(w3, a.x, acc.x); acc.y = fmaf(w3, a.y, acc.y);
            acc.z = fmaf(w3, b.x, acc.z); acc.w = fmaf(w3, b.y, acc.w);
        }
        for (; e < end; e++) {
            int2 r0 = __ldg(&csr[e]);
            uint2 q0 = __ldg((const uint2*)(S + (size_t)r0.x * 128) + lane);
            float w0 = __int_as_float(r0.y);
            float2 a = __half22float2(*(__half2*)&q0.x);
            float2 b = __half22float2(*(__half2*)&q0.y);
            acc.x = fmaf(w0, a.x, acc.x); acc.y = fmaf(w0, a.y, acc.y);
            acc.z = fmaf(w0, b.x, acc.z); acc.w = fmaf(w0, b.y, acc.w);
        }
        acc.x = fmaxf(acc.x, 0.f); acc.y = fmaxf(acc.y, 0.f);
        acc.z = fmaxf(acc.z, 0.f); acc.w = fmaxf(acc.w, 0.f);
        uint2 o;
        __half2 h0 = __floats2half2_rn(acc.x, acc.y);
        __half2 h1 = __floats2half2_rn(acc.z, acc.w);
        o.x = *(unsigned*)&h0;
        o.y = *(unsigned*)&h1;
        ((uint2*)(outA + (size_t)warp * 128))[lane] = o;
    } else {
        float2 acc = __ldg((const float2*)bias + lane);
        int e = start;
        for (; e + 3 < end; e += 4) {
            int2 r0 = __ldg(&csr[e]);
            int2 r1 = __ldg(&csr[e + 1]);
            int2 r2 = __ldg(&csr[e + 2]);
            int2 r3 = __ldg(&csr[e + 3]);
            unsigned q0 = __ldg((const unsigned*)(S + (size_t)r0.x * 64) + lane);
            unsigned q1 = __ldg((const unsigned*)(S + (size_t)r1.x * 64) + lane);
            unsigned q2 = __ldg((const unsigned*)(S + (size_t)r2.x * 64) + lane);
            unsigned q3 = __ldg((const unsigned*)(S + (size_t)r3.x * 64) + lane);
            float w0 = __int_as_float(r0.y), w1 = __int_as_float(r1.y);
            float w2 = __int_as_float(r2.y), w3 = __int_as_float(r3.y);
            float2 v;
            v = __half22float2(*(__half2*)&q0);
            acc.x = fmaf(w0, v.x, acc.x); acc.y = fmaf(w0, v.y, acc.y);
            v = __half22float2(*(__half2*)&q1);
            acc.x = fmaf(w1, v.x, acc.x); acc.y = fmaf(w1, v.y, acc.y);
            v = __half22float2(*(__half2*)&q2);
            acc.x = fmaf(w2, v.x, acc.x); acc.y = fmaf(w2, v.y, acc.y);
            v = __half22float2(*(__half2*)&q3);
            acc.x = fmaf(w3, v.x, acc.x); acc.y = fmaf(w3, v.y, acc.y);
        }
        for (; e < end; e++) {
            int2 r0 = __ldg(&csr[e]);
            unsigned q0 = __ldg((const unsigned*)(S + (size_t)r0.x * 64) + lane);
            float w0 = __int_as_float(r0.y);
            float2 v = __half22float2(*(__half2*)&q0);
            acc.x = fmaf(w0, v.x, acc.x); acc.y = fmaf(w0, v.y, acc.y);
        }
        acc.x = fmaxf(acc.x, 0.f); acc.y = fmaxf(acc.y, 0.f);
        __half2 h0 = __floats2half2_rn(acc.x, acc.y);
        ((unsigned*)(outA + (size_t)warp * 64))[lane] = *(unsigned*)&h0;
    }
}

// ---------------------------------------------------------------------------
// Final-layer SpMM: fp16 gather (4-way unrolled, default-cached), fp32 out.
// ---------------------------------------------------------------------------
__global__ void spmm_final_kernel(const __half* __restrict__ S, const int2* __restrict__ csr,
                                  const int* __restrict__ rowptr, const float* __restrict__ bias,
                                  float* __restrict__ out) {
    int warp = (blockIdx.x * blockDim.x + threadIdx.x) >> 5;
    int lane = threadIdx.x & 31;
    if (warp >= NN) return;
    int start = __ldg(&rowptr[warp]);
    int end = __ldg(&rowptr[warp + 1]);
    float2 acc = __ldg((const float2*)bias + lane);
    int e = start;
    for (; e + 3 < end; e += 4) {
        int2 r0 = __ldg(&csr[e]);
        int2 r1 = __ldg(&csr[e + 1]);
        int2 r2 = __ldg(&csr[e + 2]);
        int2 r3 = __ldg(&csr[e + 3]);
        unsigned q0 = __ldg((const unsigned*)(S + (size_t)r0.x * 64) + lane);
        unsigned q1 = __ldg((const unsigned*)(S + (size_t)r1.x * 64) + lane);
        unsigned q2 = __ldg((const unsigned*)(S + (size_t)r2.x * 64) + lane);
        unsigned q3 = __ldg((const unsigned*)(S + (size_t)r3.x * 64) + lane);
        float w0 = __int_as_float(r0.y), w1 = __int_as_float(r1.y);
        float w2 = __int_as_float(r2.y), w3 = __int_as_float(r3.y);
        float2 v;
        v = __half22float2(*(__half2*)&q0);
        acc.x = fmaf(w0, v.x, acc.x); acc.y = fmaf(w0, v.y, acc.y);
        v = __half22float2(*(__half2*)&q1);
        acc.x = fmaf(w1, v.x, acc.x); acc.y = fmaf(w1, v.y, acc.y);
        v = __half22float2(*(__half2*)&q2);
        acc.x = fmaf(w2, v.x, acc.x); acc.y = fmaf(w2, v.y, acc.y);
        v = __half22float2(*(__half2*)&q3);
        acc.x = fmaf(w3, v.x, acc.x); acc.y = fmaf(w3, v.y, acc.y);
    }
    for (; e < end; e++) {
        int2 r0 = __ldg(&csr[e]);
        unsigned q0 = __ldg((const unsigned*)(S + (size_t)r0.x * 64) + lane);
        float w0 = __int_as_float(r0.y);
        float2 v = __half22float2(*(__half2*)&q0);
        acc.x = fmaf(w0, v.x, acc.x); acc.y = fmaf(w0, v.y, acc.y);
    }
    *((float2*)(out + (size_t)warp * 64) + lane) = acc;
}

// ---------------------------------------------------------------------------
extern "C" void kernel_launch(void* const* d_in, const int* in_sizes, int n_in,
                              void* d_out, int out_size) {
    const float* x    = (const float*)d_in[0];
    const int*   esrc = (const int*)d_in[1];
    const int*   edst = (const int*)d_in[2];
    const float* ew   = (const float*)d_in[3];
    const float* W1   = (const float*)d_in[4];
    const float* b1   = (const float*)d_in[5];
    const float* W2   = (const float*)d_in[6];
    const float* b2   = (const float*)d_in[7];
    const float* W3   = (const float*)d_in[8];
    const float* b3   = (const float*)d_in[9];
    float* out = (float*)d_out;

    __half *S1h, *A1h, *S2h, *A2h, *S3h, *Wh;
    int *cnt, *pre, *bsum, *btop, *rowptr, *cursor;
    int2* csr;
    cudaGetSymbolAddress((void**)&S1h, g_S1h);
    cudaGetSymbolAddress((void**)&A1h, g_A1h);
    cudaGetSymbolAddress((void**)&S2h, g_S2h);
    cudaGetSymbolAddress((void**)&A2h, g_A2h);
    cudaGetSymbolAddress((void**)&S3h, g_S3h);
    cudaGetSymbolAddress((void**)&Wh, g_Wh);
    cudaGetSymbolAddress((void**)&cnt, g_cnt);
    cudaGetSymbolAddress((void**)&pre, g_pre);
    cudaGetSymbolAddress((void**)&bsum, g_bsum);
    cudaGetSymbolAddress((void**)&btop, g_btop);
    cudaGetSymbolAddress((void**)&rowptr, g_rowptr);
    cudaGetSymbolAddress((void**)&cursor, g_cursor);
    cudaGetSymbolAddress((void**)&csr, g_csr);

    static cudaStream_t s2strm = nullptr;
    static cudaEvent_t evFork = nullptr, evJoin = nullptr;
    if (s2strm == nullptr) {
        cudaStreamCreateWithFlags(&s2strm, cudaStreamNonBlocking);
        cudaEventCreateWithFlags(&evFork, cudaEventDisableTiming);
        cudaEventCreateWithFlags(&evJoin, cudaEventDisableTiming);
    }

    const int E = NE, M = NN;
    const int gx = (M + 127) / 128;

    cudaFuncSetAttribute(gemm_mma_kernel<128, 256, 0>,
                         cudaFuncAttributeMaxDynamicSharedMemorySize, 40960);
    cudaFuncSetAttribute(gemm_mma_kernel<64, 128, 1>,
                         cudaFuncAttributeMaxDynamicSharedMemorySize, 30720);
    cudaFuncSetAttribute(gemm_mma_kernel<64, 64, 1>,
                         cudaFuncAttributeMaxDynamicSharedMemorySize, 30720);

    // ----- Fork: CSR build + W2/W3 converts on side stream -----
    cudaEventRecord(evFork, 0);
    cudaStreamWaitEvent(s2strm, evFork, 0);
    zero_kernel<<<(NN + 511) / 512, 512, 0, s2strm>>>(cnt, NN);
    count_kernel<<<(E + 511) / 512, 512, 0, s2strm>>>(edst, cnt, E);
    scan_block_kernel<<<NBLK_SCAN, 1024, 0, s2strm>>>(cnt, pre, bsum, NN);
    scan_block_kernel<<<1, 1024, 0, s2strm>>>(bsum, btop, nullptr, NBLK_SCAN);
    add_offsets_kernel<<<(NN + 511) / 512, 512, 0, s2strm>>>(pre, btop, rowptr, cursor, NN);
    scatter_kernel<<<(E + 511) / 512, 512, 0, s2strm>>>(esrc, edst, ew, cursor, csr, E);
    wconv_kernel<<<(128 * 64 + 255) / 256, 256, 0, s2strm>>>(W2, Wh + 32768, 128, 64);
    wconv_kernel<<<(64 * 64 + 255) / 256, 256, 0, s2strm>>>(W3, Wh + 40960, 64, 64);
    cudaEventRecord(evJoin, s2strm);

    // ----- Main: W1 convert + GEMM1 (fp32 x -> fp16 S1) -----
    wconv_kernel<<<(256 * 128 + 255) / 256, 256>>>(W1, Wh, 256, 128);
    gemm_mma_kernel<128, 256, 0><<<gx, 256, 40960>>>(x, Wh, S1h, M);

    // ----- Join, then Layer 1 SpMM -----
    cudaStreamWaitEvent(0, evJoin, 0);
    spmm_h_kernel<128><<<(NN + 7) / 8, 256>>>(S1h, csr, rowptr, b1, A1h);

    // ----- Layer 2 -----
    gemm_mma_kernel<64, 128, 1><<<gx, 256, 30720>>>(A1h, Wh + 32768, S2h, M);
    spmm_h_kernel<64><<<(NN + 7) / 8, 256>>>(S2h, csr, rowptr, b2, A2h);

    // ----- Layer 3 -----
    gemm_mma_kernel<64, 64, 1><<<gx, 256, 30720>>>(A2h, Wh + 40960, S3h, M);
    spmm_final_kernel<<<(NN + 7) / 8, 256>>>(S3h, csr, rowptr, b3, out);
}